// round 1
// baseline (speedup 1.0000x reference)
#include <cuda_runtime.h>
#include <cuda_bf16.h>
#include <math.h>
#include <stdint.h>

// Problem shape (fixed by setup_inputs)
#define N_ROWS 4096
#define D_DIM  1024
#define NT     32      // number of 128-wide column tiles
#define BM 128
#define BN 128
#define BK 32
#define SK 40          // padded smem row stride (bf16 elems): conflict-free ldmatrix

// Scratch: __device__ globals (no cudaMalloc allowed)
static __device__ __nv_bfloat16 g_z1n[N_ROWS * D_DIM];
static __device__ __nv_bfloat16 g_z2n[N_ROWS * D_DIM];
static __device__ float  g_partial[N_ROWS * NT];
static __device__ float  g_diag[N_ROWS];
static __device__ double g_lossrow[N_ROWS];

__device__ __forceinline__ float ex2f(float x) {
    float y;
    asm("ex2.approx.f32 %0, %1;" : "=f"(y) : "f"(x));
    return y;
}

// ---------------------------------------------------------------------------
// Kernel 1: L2-normalize rows of z1 and z2, emit bf16
// grid = 8192 (4096 rows x 2 matrices), block = 256
// ---------------------------------------------------------------------------
__global__ void normalize_kernel(const float* __restrict__ z1,
                                 const float* __restrict__ z2)
{
    int b = blockIdx.x;
    int mat = b >> 12;
    int row = b & (N_ROWS - 1);
    const float* src = mat ? z2 : z1;
    __nv_bfloat16* dst = mat ? g_z2n : g_z1n;

    int t = threadIdx.x;  // 256 threads, 4 floats each
    float4 v = reinterpret_cast<const float4*>(src + (size_t)row * D_DIM)[t];
    float s = v.x * v.x + v.y * v.y + v.z * v.z + v.w * v.w;
    #pragma unroll
    for (int o = 16; o > 0; o >>= 1) s += __shfl_xor_sync(0xffffffffu, s, o);

    __shared__ float sh[8];
    if ((t & 31) == 0) sh[t >> 5] = s;
    __syncthreads();
    if (t < 8) {
        float x = sh[t];
        #pragma unroll
        for (int o = 4; o > 0; o >>= 1) x += __shfl_xor_sync(0xffu, x, o);
        if (t == 0) sh[0] = x;
    }
    __syncthreads();
    float inv = 1.0f / fmaxf(sqrtf(sh[0]), 1e-12f);

    __nv_bfloat162 lo = __floats2bfloat162_rn(v.x * inv, v.y * inv);
    __nv_bfloat162 hi = __floats2bfloat162_rn(v.z * inv, v.w * inv);
    uint2 pk;
    pk.x = reinterpret_cast<unsigned&>(lo);
    pk.y = reinterpret_cast<unsigned&>(hi);
    *reinterpret_cast<uint2*>(dst + (size_t)row * D_DIM + t * 4) = pk;
}

// ---------------------------------------------------------------------------
// Kernel 2: fused bf16 GEMM (logits) + exp + per-row partial sums + diagonal
// grid = (32 colTiles, 32 rowTiles), block = 256 (8 warps; warp tile 64x32)
// ---------------------------------------------------------------------------
__global__ void __launch_bounds__(256, 2) gemm_lse_kernel()
{
    __shared__ __nv_bfloat16 As[2][BM * SK];
    __shared__ __nv_bfloat16 Bs[2][BN * SK];
    __shared__ float sRed[4][BM];

    const int tid  = threadIdx.x;
    const int lane = tid & 31;
    const int warp = tid >> 5;
    const int wm   = warp >> 2;   // 0..1  -> 64 rows per warp
    const int wn   = warp & 3;    // 0..3  -> 32 cols per warp
    const int rowBase = blockIdx.y * BM;
    const int colBase = blockIdx.x * BN;

    float acc[4][4][4];
    #pragma unroll
    for (int mi = 0; mi < 4; mi++)
        #pragma unroll
        for (int ni = 0; ni < 4; ni++)
            #pragma unroll
            for (int c = 0; c < 4; c++) acc[mi][ni][c] = 0.f;

    // global->smem copy mapping: each thread owns 2 x 16B chunks per matrix
    const int r0 = tid >> 2;            // rows 0..63
    const int r1 = r0 + 64;             // rows 64..127
    const int cc = (tid & 3) * 8;       // k-offset (8 bf16 = 16B)

    const __nv_bfloat16* ga0 = g_z1n + (size_t)(rowBase + r0) * D_DIM + cc;
    const __nv_bfloat16* ga1 = g_z1n + (size_t)(rowBase + r1) * D_DIM + cc;
    const __nv_bfloat16* gb0 = g_z2n + (size_t)(colBase + r0) * D_DIM + cc;
    const __nv_bfloat16* gb1 = g_z2n + (size_t)(colBase + r1) * D_DIM + cc;

    const int s0 = r0 * SK + cc;
    const int s1 = r1 * SK + cc;

    // preload tile 0
    {
        uint4 a0 = *reinterpret_cast<const uint4*>(ga0);
        uint4 a1 = *reinterpret_cast<const uint4*>(ga1);
        uint4 b0 = *reinterpret_cast<const uint4*>(gb0);
        uint4 b1 = *reinterpret_cast<const uint4*>(gb1);
        *reinterpret_cast<uint4*>(&As[0][s0]) = a0;
        *reinterpret_cast<uint4*>(&As[0][s1]) = a1;
        *reinterpret_cast<uint4*>(&Bs[0][s0]) = b0;
        *reinterpret_cast<uint4*>(&Bs[0][s1]) = b1;
    }
    __syncthreads();

    int buf = 0;
    const int KT = D_DIM / BK;  // 32
    for (int kt = 0; kt < KT; kt++) {
        uint4 na0, na1, nb0, nb1;
        if (kt + 1 < KT) {
            int ko = (kt + 1) * BK;
            na0 = *reinterpret_cast<const uint4*>(ga0 + ko);
            na1 = *reinterpret_cast<const uint4*>(ga1 + ko);
            nb0 = *reinterpret_cast<const uint4*>(gb0 + ko);
            nb1 = *reinterpret_cast<const uint4*>(gb1 + ko);
        }

        uint32_t aBase = (uint32_t)__cvta_generic_to_shared(&As[buf][0]);
        uint32_t bBase = (uint32_t)__cvta_generic_to_shared(&Bs[buf][0]);

        #pragma unroll
        for (int ks = 0; ks < 2; ks++) {
            uint32_t af[4][4];
            #pragma unroll
            for (int mi = 0; mi < 4; mi++) {
                int row = wm * 64 + mi * 16 + (lane & 15);
                int kof = ks * 16 + ((lane >> 4) << 3);
                uint32_t addr = aBase + (row * SK + kof) * 2;
                asm volatile("ldmatrix.sync.aligned.m8n8.x4.shared.b16 {%0,%1,%2,%3}, [%4];"
                             : "=r"(af[mi][0]), "=r"(af[mi][1]),
                               "=r"(af[mi][2]), "=r"(af[mi][3])
                             : "r"(addr));
            }
            uint32_t bf[4][2];
            #pragma unroll
            for (int nb = 0; nb < 2; nb++) {
                int nrow = wn * 32 + nb * 16 + (lane & 7) + ((lane >> 4) & 1) * 8;
                int kof = ks * 16 + ((lane >> 3) & 1) * 8;
                uint32_t addr = bBase + (nrow * SK + kof) * 2;
                uint32_t q0, q1, q2, q3;
                asm volatile("ldmatrix.sync.aligned.m8n8.x4.shared.b16 {%0,%1,%2,%3}, [%4];"
                             : "=r"(q0), "=r"(q1), "=r"(q2), "=r"(q3)
                             : "r"(addr));
                bf[2 * nb][0] = q0; bf[2 * nb][1] = q1;
                bf[2 * nb + 1][0] = q2; bf[2 * nb + 1][1] = q3;
            }
            #pragma unroll
            for (int mi = 0; mi < 4; mi++)
                #pragma unroll
                for (int ni = 0; ni < 4; ni++)
                    asm volatile(
                        "mma.sync.aligned.m16n8k16.row.col.f32.bf16.bf16.f32 "
                        "{%0,%1,%2,%3}, {%4,%5,%6,%7}, {%8,%9}, {%0,%1,%2,%3};"
                        : "+f"(acc[mi][ni][0]), "+f"(acc[mi][ni][1]),
                          "+f"(acc[mi][ni][2]), "+f"(acc[mi][ni][3])
                        : "r"(af[mi][0]), "r"(af[mi][1]), "r"(af[mi][2]), "r"(af[mi][3]),
                          "r"(bf[ni][0]), "r"(bf[ni][1]));
        }

        if (kt + 1 < KT) {
            int nbuf = buf ^ 1;
            *reinterpret_cast<uint4*>(&As[nbuf][s0]) = na0;
            *reinterpret_cast<uint4*>(&As[nbuf][s1]) = na1;
            *reinterpret_cast<uint4*>(&Bs[nbuf][s0]) = nb0;
            *reinterpret_cast<uint4*>(&Bs[nbuf][s1]) = nb1;
        }
        __syncthreads();
        buf ^= 1;
    }

    // Epilogue: e = exp(logit) = exp2(acc * log2(e)/T); per-row partial sums.
    // logit magnitudes <= ~2.6, no max subtraction needed.
    const float K1   = 20.609929155556624f;   // log2(e)/0.07
    const float INVT = 14.285714285714286f;   // 1/0.07
    const bool diagBlk = (rowBase == colBase);

    float rs[4][2];
    #pragma unroll
    for (int mi = 0; mi < 4; mi++) { rs[mi][0] = 0.f; rs[mi][1] = 0.f; }

    #pragma unroll
    for (int mi = 0; mi < 4; mi++) {
        #pragma unroll
        for (int ni = 0; ni < 4; ni++) {
            float e0 = ex2f(acc[mi][ni][0] * K1);
            float e1 = ex2f(acc[mi][ni][1] * K1);
            float e2 = ex2f(acc[mi][ni][2] * K1);
            float e3 = ex2f(acc[mi][ni][3] * K1);
            rs[mi][0] += e0 + e1;
            rs[mi][1] += e2 + e3;
            if (diagBlk) {
                int lr = wm * 64 + mi * 16 + (lane >> 2);
                int lc = wn * 32 + ni * 8 + 2 * (lane & 3);
                if (lr == lc)         g_diag[rowBase + lr]     = acc[mi][ni][0] * INVT;
                if (lr == lc + 1)     g_diag[rowBase + lr]     = acc[mi][ni][1] * INVT;
                if (lr + 8 == lc)     g_diag[rowBase + lr + 8] = acc[mi][ni][2] * INVT;
                if (lr + 8 == lc + 1) g_diag[rowBase + lr + 8] = acc[mi][ni][3] * INVT;
            }
        }
    }

    // reduce across the 4 lanes of each quad (same row, different cols)
    #pragma unroll
    for (int mi = 0; mi < 4; mi++)
        #pragma unroll
        for (int h = 0; h < 2; h++) {
            float v = rs[mi][h];
            v += __shfl_xor_sync(0xffffffffu, v, 1);
            v += __shfl_xor_sync(0xffffffffu, v, 2);
            if ((lane & 3) == 0)
                sRed[wn][wm * 64 + mi * 16 + h * 8 + (lane >> 2)] = v;
        }
    __syncthreads();

    // combine the 4 warp-columns; deterministic write (one writer per slot)
    if (tid < BM) {
        float p = sRed[0][tid] + sRed[1][tid] + sRed[2][tid] + sRed[3][tid];
        g_partial[(size_t)(rowBase + tid) * NT + blockIdx.x] = p;
    }
}

// ---------------------------------------------------------------------------
// Kernel 3: per-row loss_i = log(sum_j exp(l_ij)) - l_ii  (double precision)
// ---------------------------------------------------------------------------
__global__ void rowloss_kernel()
{
    int row = blockIdx.x * 256 + threadIdx.x;
    const float4* p = reinterpret_cast<const float4*>(g_partial + (size_t)row * NT);
    double s = 0.0;
    #pragma unroll
    for (int i = 0; i < 8; i++) {
        float4 v = p[i];
        s += (double)v.x + (double)v.y + (double)v.z + (double)v.w;
    }
    g_lossrow[row] = log(s) - (double)g_diag[row];
}

// ---------------------------------------------------------------------------
// Kernel 4: mean over rows -> scalar
// ---------------------------------------------------------------------------
__global__ void reduce_kernel(float* __restrict__ out)
{
    int t = threadIdx.x;
    double s = 0.0;
    for (int i = t; i < N_ROWS; i += 256) s += g_lossrow[i];
    #pragma unroll
    for (int o = 16; o > 0; o >>= 1) s += __shfl_xor_sync(0xffffffffu, s, o);
    __shared__ double sh[8];
    if ((t & 31) == 0) sh[t >> 5] = s;
    __syncthreads();
    if (t < 8) {
        double x = sh[t];
        #pragma unroll
        for (int o = 4; o > 0; o >>= 1) x += __shfl_xor_sync(0xffu, x, o);
        if (t == 0) out[0] = (float)(x / (double)N_ROWS);
    }
}

// ---------------------------------------------------------------------------
extern "C" void kernel_launch(void* const* d_in, const int* in_sizes, int n_in,
                              void* d_out, int out_size)
{
    const float* z1 = (const float*)d_in[0];
    const float* z2 = (const float*)d_in[1];
    float* out = (float*)d_out;

    normalize_kernel<<<2 * N_ROWS, 256>>>(z1, z2);
    dim3 grid(N_ROWS / BN, N_ROWS / BM);
    gemm_lse_kernel<<<grid, 256>>>();
    rowloss_kernel<<<N_ROWS / 256, 256>>>();
    reduce_kernel<<<1, 256>>>(out);
}

// round 3
// speedup vs baseline: 2.5731x; 2.5731x over previous
#include <cuda_runtime.h>
#include <cuda.h>
#include <cuda_bf16.h>
#include <math.h>
#include <stdint.h>
#include <dlfcn.h>

// ---- feature probe: tcgen05 needs arch-specific (sm_103a) compilation ----
#if defined(__CUDA_ARCH_FEAT_SM103_ALL) || \
    (defined(__CUDA_ARCH_SPECIFIC__) && (__CUDA_ARCH_SPECIFIC__ == 1030))
#define HAS_TC 1
#else
#define HAS_TC 0
#endif

// ---------------- problem constants ----------------
#define N_ROWS 4096
#define D_DIM  1024
#define NT     32      // g_partial slots per row (mma path: 32 x 128-wide tiles)

// tcgen05 path tiling
#define TILE_M 128
#define TILE_N 256
#define CHUNK_K 64                       // bf16 elems per k-chunk = 128 bytes
#define NUM_CHUNKS (D_DIM / CHUNK_K)     // 16
#define NT_TC (N_ROWS / TILE_N)          // 16 column tiles
#define NUM_TILES ((N_ROWS / TILE_M) * NT_TC)  // 512
#define GRID_GEMM 128
#define TILES_PER_CTA (NUM_TILES / GRID_GEMM)  // 4
#define STAGES 4

// mma.sync fallback tiling
#define BM 128
#define BN 128
#define BK 32
#define SK 40

// tcgen05 SMEM layout
#define SMEM_TMEM   0
#define SMEM_FULL   8
#define SMEM_EMPTY  40
#define SMEM_TDONE  72
#define SMEM_DFREE  88
#define SMEM_STAGE  1024
#define STAGE_BYTES 49152  // A 16KB + B 32KB
#define A_OFF 0
#define B_OFF 16384
#define SMEM_TOTAL (SMEM_STAGE + STAGES * STAGE_BYTES)  // 197632

// idesc: kind::f16, dtype F32, atype/btype BF16, N=256, M=128
#define MMA_IDESC ((1u<<4)|(1u<<7)|(1u<<10)|((TILE_N/8)<<17)|((TILE_M/16)<<24))

// SW128 K-major smem descriptor base (layout=2, version=1, SBO=64, LBO=1)
static __device__ constexpr uint64_t DESC_BASE =
    (uint64_t(2) << 61) | (uint64_t(1) << 46) | (uint64_t(64) << 32) | (uint64_t(1) << 16);

// ---------------- device scratch (no cudaMalloc allowed) ----------------
// NOTE: g_partial relies on CUDA's zero-init of __device__ globals: the tc path
// writes only slots [0,16) per row; slots [16,32) stay 0 forever (the two GEMM
// paths are compile-time mutually exclusive).
__device__ __align__(1024) __nv_bfloat16 g_z1n[N_ROWS * D_DIM];
__device__ __align__(1024) __nv_bfloat16 g_z2n[N_ROWS * D_DIM];
__device__ float  g_partial[N_ROWS * NT];
__device__ float  g_diag[N_ROWS];
__device__ double g_blocksum[16];

// ---------------- PTX helpers ----------------
__device__ __forceinline__ uint32_t smem_u32(const void* p) {
    uint32_t a;
    asm("{ .reg .u64 t; cvta.to.shared.u64 t, %1; cvt.u32.u64 %0, t; }" : "=r"(a) : "l"(p));
    return a;
}
__device__ __forceinline__ float ex2f(float x) {
    float y; asm("ex2.approx.f32 %0, %1;" : "=f"(y) : "f"(x)); return y;
}

#if HAS_TC
__device__ __forceinline__ uint32_t elect_one() {
    uint32_t p;
    asm volatile("{ .reg .pred p; elect.sync _|p, 0xFFFFFFFF; selp.b32 %0,1,0,p; }" : "=r"(p));
    return p;
}
__device__ __forceinline__ void mbar_init(uint32_t a, uint32_t cnt) {
    asm volatile("mbarrier.init.shared.b64 [%0], %1;" :: "r"(a), "r"(cnt) : "memory");
}
__device__ __forceinline__ void mbar_expect_tx(uint32_t a, uint32_t bytes) {
    asm volatile("mbarrier.arrive.expect_tx.shared.b64 _, [%0], %1;" :: "r"(a), "r"(bytes) : "memory");
}
__device__ __forceinline__ void mbar_arrive(uint32_t a) {
    asm volatile("mbarrier.arrive.shared.b64 _, [%0];" :: "r"(a) : "memory");
}
__device__ __forceinline__ void mbar_wait_acq(uint32_t a, uint32_t ph) {
    asm volatile("{ .reg .pred P;\n"
                 "W_%=: mbarrier.try_wait.parity.acquire.cta.shared::cta.b64 P, [%0], %1;\n"
                 "@!P bra W_%=; }" :: "r"(a), "r"(ph) : "memory");
}
__device__ __forceinline__ void mbar_wait_rlx(uint32_t a, uint32_t ph) {
    asm volatile("{ .reg .pred P;\n"
                 "W_%=: mbarrier.try_wait.parity.relaxed.cta.shared::cta.b64 P, [%0], %1;\n"
                 "@!P bra W_%=; }" :: "r"(a), "r"(ph) : "memory");
}
__device__ __forceinline__ void tma2d(uint32_t dst, const CUtensorMap* m, int x, int y, uint32_t mbar) {
    asm volatile("cp.async.bulk.tensor.2d.shared::cta.global.tile.mbarrier::complete_tx::bytes "
                 "[%0], [%1, {%2, %3}], [%4];"
                 :: "r"(dst), "l"(m), "r"(x), "r"(y), "r"(mbar) : "memory");
}
__device__ __forceinline__ void tc_alloc(uint32_t smem_res, uint32_t ncols) {
    asm volatile("tcgen05.alloc.cta_group::1.sync.aligned.shared::cta.b32 [%0], %1;"
                 :: "r"(smem_res), "r"(ncols) : "memory");
}
__device__ __forceinline__ void tc_dealloc(uint32_t tmem, uint32_t ncols) {
    asm volatile("tcgen05.dealloc.cta_group::1.sync.aligned.b32 %0, %1;" :: "r"(tmem), "r"(ncols));
}
__device__ __forceinline__ void tc_relinq() {
    asm volatile("tcgen05.relinquish_alloc_permit.cta_group::1.sync.aligned;");
}
__device__ __forceinline__ void tc_commit(uint32_t mbar) {
    asm volatile("tcgen05.commit.cta_group::1.mbarrier::arrive::one.shared::cluster.b64 [%0];"
                 :: "r"(mbar) : "memory");
}
__device__ __forceinline__ void tc_fence_after() {
    asm volatile("tcgen05.fence::after_thread_sync;" ::: "memory");
}
__device__ __forceinline__ void tc_fence_before() {
    asm volatile("tcgen05.fence::before_thread_sync;" ::: "memory");
}
__device__ __forceinline__ void tc_wait_ld() {
    asm volatile("tcgen05.wait::ld.sync.aligned;" ::: "memory");
}
__device__ __forceinline__ void fence_proxy_async_cta() {
    asm volatile("fence.proxy.async.shared::cta;" ::: "memory");
}
__device__ __forceinline__ void mma_f16_ss(uint32_t d, uint64_t a, uint64_t b, uint32_t idesc, int acc) {
    asm volatile("{ .reg .pred p; setp.ne.u32 p, %4, 0;\n"
                 "tcgen05.mma.cta_group::1.kind::f16 [%0], %1, %2, %3, {%5,%5,%5,%5}, p; }"
                 :: "r"(d), "l"(a), "l"(b), "r"(idesc), "r"(acc), "r"(0u) : "memory");
}
__device__ __forceinline__ void ldtm_x32(uint32_t* r, uint32_t addr) {
    asm volatile("tcgen05.ld.sync.aligned.32x32b.x32.b32 "
                 "{%0,%1,%2,%3,%4,%5,%6,%7,%8,%9,%10,%11,%12,%13,%14,%15,"
                 "%16,%17,%18,%19,%20,%21,%22,%23,%24,%25,%26,%27,%28,%29,%30,%31}, [%32];"
                 : "=r"(r[0]), "=r"(r[1]), "=r"(r[2]), "=r"(r[3]), "=r"(r[4]), "=r"(r[5]),
                   "=r"(r[6]), "=r"(r[7]), "=r"(r[8]), "=r"(r[9]), "=r"(r[10]), "=r"(r[11]),
                   "=r"(r[12]), "=r"(r[13]), "=r"(r[14]), "=r"(r[15]), "=r"(r[16]), "=r"(r[17]),
                   "=r"(r[18]), "=r"(r[19]), "=r"(r[20]), "=r"(r[21]), "=r"(r[22]), "=r"(r[23]),
                   "=r"(r[24]), "=r"(r[25]), "=r"(r[26]), "=r"(r[27]), "=r"(r[28]), "=r"(r[29]),
                   "=r"(r[30]), "=r"(r[31])
                 : "r"(addr));
}
#endif  // HAS_TC

// ---------------------------------------------------------------------------
// Kernel 1: L2-normalize rows of z1, z2 -> bf16
// ---------------------------------------------------------------------------
__global__ void normalize_kernel(const float* __restrict__ z1,
                                 const float* __restrict__ z2)
{
    int b = blockIdx.x;
    int mat = b >> 12;
    int row = b & (N_ROWS - 1);
    const float* src = mat ? z2 : z1;
    __nv_bfloat16* dst = mat ? g_z2n : g_z1n;

    int t = threadIdx.x;
    float4 v = reinterpret_cast<const float4*>(src + (size_t)row * D_DIM)[t];
    float s = v.x * v.x + v.y * v.y + v.z * v.z + v.w * v.w;
    #pragma unroll
    for (int o = 16; o > 0; o >>= 1) s += __shfl_xor_sync(0xffffffffu, s, o);
    __shared__ float sh[8];
    if ((t & 31) == 0) sh[t >> 5] = s;
    __syncthreads();
    if (t < 8) {
        float x = sh[t];
        #pragma unroll
        for (int o = 4; o > 0; o >>= 1) x += __shfl_xor_sync(0xffu, x, o);
        if (t == 0) sh[0] = x;
    }
    __syncthreads();
    float inv = 1.0f / fmaxf(sqrtf(sh[0]), 1e-12f);

    __nv_bfloat162 lo = __floats2bfloat162_rn(v.x * inv, v.y * inv);
    __nv_bfloat162 hi = __floats2bfloat162_rn(v.z * inv, v.w * inv);
    uint2 pk;
    pk.x = reinterpret_cast<unsigned&>(lo);
    pk.y = reinterpret_cast<unsigned&>(hi);
    *reinterpret_cast<uint2*>(dst + (size_t)row * D_DIM + t * 4) = pk;
}

// ---------------------------------------------------------------------------
// Kernel 2a: persistent tcgen05 GEMM + fused epilogue (compiled only if
// the device pass is arch-specific sm_103a; otherwise an empty stub).
// ---------------------------------------------------------------------------
__global__ void __launch_bounds__(192, 1)
gemm_lse_tc_kernel(const __grid_constant__ CUtensorMap tmA,
                   const __grid_constant__ CUtensorMap tmB)
{
#if HAS_TC
    extern __shared__ char smem[];
    const uint32_t sb = smem_u32(smem);
    const int tid  = threadIdx.x;
    const int warp = tid >> 5;
    const int lane = tid & 31;
    const int bid  = blockIdx.x;

    if (warp == 5) tc_alloc(sb + SMEM_TMEM, 512);
    if (tid == 0) {
        #pragma unroll
        for (int s = 0; s < STAGES; s++) {
            mbar_init(sb + SMEM_FULL  + s * 8, 1);
            mbar_init(sb + SMEM_EMPTY + s * 8, 1);
        }
        mbar_init(sb + SMEM_TDONE,     1);
        mbar_init(sb + SMEM_TDONE + 8, 1);
        mbar_init(sb + SMEM_DFREE,     4);
        mbar_init(sb + SMEM_DFREE + 8, 4);
        fence_proxy_async_cta();
    }
    __syncthreads();

    uint32_t tbase;
    asm volatile("ld.shared.b32 %0, [%1];" : "=r"(tbase) : "r"(sb + SMEM_TMEM));

    if (warp == 4) {
        if (elect_one()) {
            int c = 0;
            for (int i = 0; i < TILES_PER_CTA; i++) {
                int t = bid + i * GRID_GEMM;
                int rowBase = (t >> 4) * TILE_M;
                int colBase = (t & 15) * TILE_N;
                for (int ch = 0; ch < NUM_CHUNKS; ch++, c++) {
                    int s = c & 3;
                    mbar_wait_rlx(sb + SMEM_EMPTY + s * 8, ((c >> 2) & 1) ^ 1);
                    mbar_expect_tx(sb + SMEM_FULL + s * 8, STAGE_BYTES);
                    uint32_t base = sb + SMEM_STAGE + s * STAGE_BYTES;
                    tma2d(base + A_OFF, &tmA, ch * CHUNK_K, rowBase, sb + SMEM_FULL + s * 8);
                    tma2d(base + B_OFF, &tmB, ch * CHUNK_K, colBase, sb + SMEM_FULL + s * 8);
                }
            }
        }
    } else if (warp == 5) {
        int c = 0;
        int phw[2] = {1, 1};
        for (int i = 0; i < TILES_PER_CTA; i++) {
            int p = i & 1;
            mbar_wait_rlx(sb + SMEM_DFREE + p * 8, phw[p]);
            phw[p] ^= 1;
            uint32_t d = tbase + p * TILE_N;
            for (int ch = 0; ch < NUM_CHUNKS; ch++, c++) {
                int s = c & 3;
                mbar_wait_acq(sb + SMEM_FULL + s * 8, (c >> 2) & 1);
                if (elect_one()) {
                    uint32_t base = sb + SMEM_STAGE + s * STAGE_BYTES;
                    uint64_t aD = DESC_BASE | (uint64_t)(((base + A_OFF) >> 4) & 0x3FFF);
                    uint64_t bD = DESC_BASE | (uint64_t)(((base + B_OFF) >> 4) & 0x3FFF);
                    #pragma unroll
                    for (int j = 0; j < 4; j++)
                        mma_f16_ss(d, aD + j * 2, bD + j * 2, MMA_IDESC, (ch > 0) | (j > 0));
                    tc_commit(sb + SMEM_EMPTY + s * 8);
                }
            }
            if (elect_one()) tc_commit(sb + SMEM_TDONE + p * 8);
        }
    } else {
        const float K1   = 20.609929155556624f;   // log2(e)/0.07
        const float INVT = 14.285714285714286f;   // 1/0.07
        int phe[2] = {0, 0};
        for (int i = 0; i < TILES_PER_CTA; i++) {
            int p = i & 1;
            int t = bid + i * GRID_GEMM;
            int rowBase = (t >> 4) * TILE_M;
            int colBase = (t & 15) * TILE_N;
            mbar_wait_acq(sb + SMEM_TDONE + p * 8, phe[p]);
            phe[p] ^= 1;
            tc_fence_after();

            int grow = rowBase + warp * 32 + lane;
            int tgtC = grow - colBase;
            bool hasD = (tgtC >= 0) && (tgtC < TILE_N);
            float dval = 0.f;
            float s0 = 0.f, s1 = 0.f, s2 = 0.f, s3 = 0.f;

            #pragma unroll
            for (int chn = 0; chn < TILE_N / 32; chn++) {
                uint32_t r[32];
                ldtm_x32(r, tbase + p * TILE_N + chn * 32);
                tc_wait_ld();
                #pragma unroll
                for (int q = 0; q < 32; q += 4) {
                    s0 += ex2f(__uint_as_float(r[q    ]) * K1);
                    s1 += ex2f(__uint_as_float(r[q + 1]) * K1);
                    s2 += ex2f(__uint_as_float(r[q + 2]) * K1);
                    s3 += ex2f(__uint_as_float(r[q + 3]) * K1);
                }
                if (hasD && ((tgtC >> 5) == chn)) dval = __uint_as_float(r[tgtC & 31]);
            }
            tc_fence_before();
            __syncwarp();
            if (lane == 0) mbar_arrive(sb + SMEM_DFREE + p * 8);

            // slots [0,16); slots [16,32) stay zero-initialized forever
            g_partial[(size_t)grow * NT + (t & 15)] = (s0 + s1) + (s2 + s3);
            if (hasD) g_diag[grow] = dval * INVT;
        }
    }

    __syncthreads();
    if (warp == 5) {
        tc_relinq();
        tc_dealloc(tbase, 512);
    }
#endif  // HAS_TC
}

// ---------------------------------------------------------------------------
// Kernel 2b: mma.sync fallback (no-op when tcgen05 path is active)
// ---------------------------------------------------------------------------
__global__ void __launch_bounds__(256, 2) gemm_lse_mma_kernel()
{
    if (HAS_TC) return;   // compile-time constant: whole kernel folds away

    __shared__ __nv_bfloat16 As[2][BM * SK];
    __shared__ __nv_bfloat16 Bs[2][BN * SK];
    __shared__ float sRed[4][BM];

    const int tid  = threadIdx.x;
    const int lane = tid & 31;
    const int warp = tid >> 5;
    const int wm   = warp >> 2;
    const int wn   = warp & 3;
    const int rowBase = blockIdx.y * BM;
    const int colBase = blockIdx.x * BN;

    float acc[4][4][4];
    #pragma unroll
    for (int mi = 0; mi < 4; mi++)
        #pragma unroll
        for (int ni = 0; ni < 4; ni++)
            #pragma unroll
            for (int c = 0; c < 4; c++) acc[mi][ni][c] = 0.f;

    const int r0 = tid >> 2;
    const int r1 = r0 + 64;
    const int cc = (tid & 3) * 8;

    const __nv_bfloat16* ga0 = g_z1n + (size_t)(rowBase + r0) * D_DIM + cc;
    const __nv_bfloat16* ga1 = g_z1n + (size_t)(rowBase + r1) * D_DIM + cc;
    const __nv_bfloat16* gb0 = g_z2n + (size_t)(colBase + r0) * D_DIM + cc;
    const __nv_bfloat16* gb1 = g_z2n + (size_t)(colBase + r1) * D_DIM + cc;

    const int s0 = r0 * SK + cc;
    const int s1 = r1 * SK + cc;

    {
        uint4 a0 = *reinterpret_cast<const uint4*>(ga0);
        uint4 a1 = *reinterpret_cast<const uint4*>(ga1);
        uint4 b0 = *reinterpret_cast<const uint4*>(gb0);
        uint4 b1 = *reinterpret_cast<const uint4*>(gb1);
        *reinterpret_cast<uint4*>(&As[0][s0]) = a0;
        *reinterpret_cast<uint4*>(&As[0][s1]) = a1;
        *reinterpret_cast<uint4*>(&Bs[0][s0]) = b0;
        *reinterpret_cast<uint4*>(&Bs[0][s1]) = b1;
    }
    __syncthreads();

    int buf = 0;
    const int KT = D_DIM / BK;
    for (int kt = 0; kt < KT; kt++) {
        uint4 na0, na1, nb0, nb1;
        if (kt + 1 < KT) {
            int ko = (kt + 1) * BK;
            na0 = *reinterpret_cast<const uint4*>(ga0 + ko);
            na1 = *reinterpret_cast<const uint4*>(ga1 + ko);
            nb0 = *reinterpret_cast<const uint4*>(gb0 + ko);
            nb1 = *reinterpret_cast<const uint4*>(gb1 + ko);
        }

        uint32_t aBase = (uint32_t)__cvta_generic_to_shared(&As[buf][0]);
        uint32_t bBase = (uint32_t)__cvta_generic_to_shared(&Bs[buf][0]);

        #pragma unroll
        for (int ks = 0; ks < 2; ks++) {
            uint32_t af[4][4];
            #pragma unroll
            for (int mi = 0; mi < 4; mi++) {
                int row = wm * 64 + mi * 16 + (lane & 15);
                int kof = ks * 16 + ((lane >> 4) << 3);
                uint32_t addr = aBase + (row * SK + kof) * 2;
                asm volatile("ldmatrix.sync.aligned.m8n8.x4.shared.b16 {%0,%1,%2,%3}, [%4];"
                             : "=r"(af[mi][0]), "=r"(af[mi][1]),
                               "=r"(af[mi][2]), "=r"(af[mi][3])
                             : "r"(addr));
            }
            uint32_t bf[4][2];
            #pragma unroll
            for (int nb = 0; nb < 2; nb++) {
                int nrow = wn * 32 + nb * 16 + (lane & 7) + ((lane >> 4) & 1) * 8;
                int kof = ks * 16 + ((lane >> 3) & 1) * 8;
                uint32_t addr = bBase + (nrow * SK + kof) * 2;
                uint32_t q0, q1, q2, q3;
                asm volatile("ldmatrix.sync.aligned.m8n8.x4.shared.b16 {%0,%1,%2,%3}, [%4];"
                             : "=r"(q0), "=r"(q1), "=r"(q2), "=r"(q3)
                             : "r"(addr));
                bf[2 * nb][0] = q0; bf[2 * nb][1] = q1;
                bf[2 * nb + 1][0] = q2; bf[2 * nb + 1][1] = q3;
            }
            #pragma unroll
            for (int mi = 0; mi < 4; mi++)
                #pragma unroll
                for (int ni = 0; ni < 4; ni++)
                    asm volatile(
                        "mma.sync.aligned.m16n8k16.row.col.f32.bf16.bf16.f32 "
                        "{%0,%1,%2,%3}, {%4,%5,%6,%7}, {%8,%9}, {%0,%1,%2,%3};"
                        : "+f"(acc[mi][ni][0]), "+f"(acc[mi][ni][1]),
                          "+f"(acc[mi][ni][2]), "+f"(acc[mi][ni][3])
                        : "r"(af[mi][0]), "r"(af[mi][1]), "r"(af[mi][2]), "r"(af[mi][3]),
                          "r"(bf[ni][0]), "r"(bf[ni][1]));
        }

        if (kt + 1 < KT) {
            int nbuf = buf ^ 1;
            *reinterpret_cast<uint4*>(&As[nbuf][s0]) = na0;
            *reinterpret_cast<uint4*>(&As[nbuf][s1]) = na1;
            *reinterpret_cast<uint4*>(&Bs[nbuf][s0]) = nb0;
            *reinterpret_cast<uint4*>(&Bs[nbuf][s1]) = nb1;
        }
        __syncthreads();
        buf ^= 1;
    }

    const float K1   = 20.609929155556624f;
    const float INVT = 14.285714285714286f;
    const bool diagBlk = (rowBase == colBase);

    float rs[4][2];
    #pragma unroll
    for (int mi = 0; mi < 4; mi++) { rs[mi][0] = 0.f; rs[mi][1] = 0.f; }

    #pragma unroll
    for (int mi = 0; mi < 4; mi++) {
        #pragma unroll
        for (int ni = 0; ni < 4; ni++) {
            float e0 = ex2f(acc[mi][ni][0] * K1);
            float e1 = ex2f(acc[mi][ni][1] * K1);
            float e2 = ex2f(acc[mi][ni][2] * K1);
            float e3 = ex2f(acc[mi][ni][3] * K1);
            rs[mi][0] += e0 + e1;
            rs[mi][1] += e2 + e3;
            if (diagBlk) {
                int lr = wm * 64 + mi * 16 + (lane >> 2);
                int lc = wn * 32 + ni * 8 + 2 * (lane & 3);
                if (lr == lc)         g_diag[rowBase + lr]     = acc[mi][ni][0] * INVT;
                if (lr == lc + 1)     g_diag[rowBase + lr]     = acc[mi][ni][1] * INVT;
                if (lr + 8 == lc)     g_diag[rowBase + lr + 8] = acc[mi][ni][2] * INVT;
                if (lr + 8 == lc + 1) g_diag[rowBase + lr + 8] = acc[mi][ni][3] * INVT;
            }
        }
    }

    #pragma unroll
    for (int mi = 0; mi < 4; mi++)
        #pragma unroll
        for (int h = 0; h < 2; h++) {
            float v = rs[mi][h];
            v += __shfl_xor_sync(0xffffffffu, v, 1);
            v += __shfl_xor_sync(0xffffffffu, v, 2);
            if ((lane & 3) == 0)
                sRed[wn][wm * 64 + mi * 16 + h * 8 + (lane >> 2)] = v;
        }
    __syncthreads();

    if (tid < BM) {
        float p = sRed[0][tid] + sRed[1][tid] + sRed[2][tid] + sRed[3][tid];
        g_partial[(size_t)(rowBase + tid) * NT + blockIdx.x] = p;
    }
}

// ---------------------------------------------------------------------------
// Kernel 3: per-row loss, one double per block (16 blocks x 256)
// ---------------------------------------------------------------------------
__global__ void rowloss_kernel()
{
    int row = blockIdx.x * 256 + threadIdx.x;
    const float4* p = reinterpret_cast<const float4*>(g_partial + (size_t)row * NT);
    double s = 0.0;
    #pragma unroll
    for (int i = 0; i < NT / 4; i++) {
        float4 v = p[i];
        s += (double)v.x + (double)v.y + (double)v.z + (double)v.w;
    }
    double loss = log(s) - (double)g_diag[row];

    int t = threadIdx.x;
    #pragma unroll
    for (int o = 16; o > 0; o >>= 1) loss += __shfl_xor_sync(0xffffffffu, loss, o);
    __shared__ double sh[8];
    if ((t & 31) == 0) sh[t >> 5] = loss;
    __syncthreads();
    if (t < 8) {
        double x = sh[t];
        #pragma unroll
        for (int o = 4; o > 0; o >>= 1) x += __shfl_xor_sync(0xffu, x, o);
        if (t == 0) g_blocksum[blockIdx.x] = x;
    }
}

// ---------------------------------------------------------------------------
// Kernel 4: final mean over 16 block sums (1 warp)
// ---------------------------------------------------------------------------
__global__ void reduce_kernel(float* __restrict__ out)
{
    int t = threadIdx.x;
    double s = (t < 16) ? g_blocksum[t] : 0.0;
    #pragma unroll
    for (int o = 16; o > 0; o >>= 1) s += __shfl_xor_sync(0xffffffffu, s, o);
    if (t == 0) out[0] = (float)(s / (double)N_ROWS);
}

// ---------------------------------------------------------------------------
extern "C" void kernel_launch(void* const* d_in, const int* in_sizes, int n_in,
                              void* d_out, int out_size)
{
    const float* z1 = (const float*)d_in[0];
    const float* z2 = (const float*)d_in[1];
    float* out = (float*)d_out;

    // Host-side TMA descriptor construction (pure computation, every call)
    void *pa = nullptr, *pb = nullptr;
    cudaGetSymbolAddress(&pa, g_z1n);
    cudaGetSymbolAddress(&pb, g_z2n);

    typedef CUresult (*EncFn)(CUtensorMap*, CUtensorMapDataType, cuuint32_t, void*,
                              const cuuint64_t*, const cuuint64_t*, const cuuint32_t*,
                              const cuuint32_t*, CUtensorMapInterleave, CUtensorMapSwizzle,
                              CUtensorMapL2promotion, CUtensorMapFloatOOBfill);
    void* h = dlopen("libcuda.so.1", RTLD_NOW | RTLD_GLOBAL);
    if (!h) h = dlopen("libcuda.so", RTLD_NOW | RTLD_GLOBAL);
    EncFn enc = h ? (EncFn)dlsym(h, "cuTensorMapEncodeTiled") : nullptr;

    CUtensorMap tmA = {}, tmB = {};
    cuuint64_t dims[2]    = {D_DIM, N_ROWS};
    cuuint64_t strides[1] = {D_DIM * 2};
    cuuint32_t boxA[2]    = {CHUNK_K, TILE_M};
    cuuint32_t boxB[2]    = {CHUNK_K, TILE_N};
    cuuint32_t es[2]      = {1, 1};
    if (enc) {
        enc(&tmA, CU_TENSOR_MAP_DATA_TYPE_BFLOAT16, 2, pa, dims, strides, boxA, es,
            CU_TENSOR_MAP_INTERLEAVE_NONE, CU_TENSOR_MAP_SWIZZLE_128B,
            CU_TENSOR_MAP_L2_PROMOTION_L2_128B, CU_TENSOR_MAP_FLOAT_OOB_FILL_NONE);
        enc(&tmB, CU_TENSOR_MAP_DATA_TYPE_BFLOAT16, 2, pb, dims, strides, boxB, es,
            CU_TENSOR_MAP_INTERLEAVE_NONE, CU_TENSOR_MAP_SWIZZLE_128B,
            CU_TENSOR_MAP_L2_PROMOTION_L2_128B, CU_TENSOR_MAP_FLOAT_OOB_FILL_NONE);
    }

    cudaFuncSetAttribute(gemm_lse_tc_kernel,
                         cudaFuncAttributeMaxDynamicSharedMemorySize, SMEM_TOTAL);

    normalize_kernel<<<2 * N_ROWS, 256>>>(z1, z2);
    gemm_lse_tc_kernel<<<GRID_GEMM, 192, SMEM_TOTAL>>>(tmA, tmB);   // no-op if !HAS_TC
    dim3 grid(N_ROWS / BN, N_ROWS / BM);
    gemm_lse_mma_kernel<<<grid, 256>>>();                            // no-op if HAS_TC
    rowloss_kernel<<<16, 256>>>();
    reduce_kernel<<<1, 32>>>(out);
}

// round 4
// speedup vs baseline: 2.7562x; 1.0712x over previous
#include <cuda_runtime.h>
#include <cuda.h>
#include <cuda_bf16.h>
#include <math.h>
#include <stdint.h>
#include <dlfcn.h>

// ---- feature probe: tcgen05/cg2 need arch-specific (sm_103a) pass ----
#if defined(__CUDA_ARCH_FEAT_SM103_ALL) || \
    (defined(__CUDA_ARCH_SPECIFIC__) && (__CUDA_ARCH_SPECIFIC__ == 1030))
#define HAS_TC 1
#else
#define HAS_TC 0
#endif

// ---------------- problem constants ----------------
#define N_ROWS 4096
#define D_DIM  1024
#define TILE   256                         // 256x256 output tiles (cg2 pair)
#define NT     (N_ROWS / TILE)             // 16 column tiles -> 16 partials/row
#define NUM_TILES (NT * NT)                // 256
#define GRID_GEMM 128                      // 64 clusters of 2
#define NUM_CLUSTERS (GRID_GEMM / 2)       // 64
#define TILES_PER_CL (NUM_TILES / NUM_CLUSTERS)  // 4
#define CHUNK_K 64                         // 128 bytes of bf16 per row chunk
#define NUM_CHUNKS (D_DIM / CHUNK_K)       // 16
#define STAGES 4

// SMEM layout (per CTA)
#define SMEM_TMEM   0
#define SMEM_FULL   8      // 4 x 8B (leader-used)
#define SMEM_EMPTY  40     // 4 x 8B
#define SMEM_TDONE  72     // 2 x 8B
#define SMEM_DFREE  88     // 2 x 8B (leader-used, count 8)
#define SMEM_STAGE  1024
#define A_OFF 0            // 128 rows x 128B = 16KB
#define B_OFF 16384        // 128 cols x 128B = 16KB
#define STAGE_BYTES 32768
#define SMEM_TOTAL (SMEM_STAGE + STAGES * STAGE_BYTES)  // 132096
#define EXPECT_BYTES (4 * 16384)   // A+B from both CTAs -> leader barrier

// idesc: kind::f16, dtype F32, atype/btype BF16, N=256, M_total=256
#define MMA_IDESC ((1u<<4)|(1u<<7)|(1u<<10)|((TILE/8)<<17)|((TILE/16)<<24))

// SW128 K-major smem descriptor base (layout=2, version=1, SBO=64, LBO=1)
static __device__ constexpr uint64_t DESC_BASE =
    (uint64_t(2) << 61) | (uint64_t(1) << 46) | (uint64_t(64) << 32) | (uint64_t(1) << 16);

// ---------------- device scratch (no cudaMalloc allowed) ----------------
__device__ __align__(1024) __nv_bfloat16 g_z1n[N_ROWS * D_DIM];
__device__ __align__(1024) __nv_bfloat16 g_z2n[N_ROWS * D_DIM];
__device__ float g_partial[N_ROWS * NT];
__device__ float g_diag[N_ROWS];

// ---------------- PTX helpers ----------------
__device__ __forceinline__ uint32_t smem_u32(const void* p) {
    uint32_t a;
    asm("{ .reg .u64 t; cvta.to.shared.u64 t, %1; cvt.u32.u64 %0, t; }" : "=r"(a) : "l"(p));
    return a;
}
__device__ __forceinline__ float ex2f(float x) {
    float y; asm("ex2.approx.f32 %0, %1;" : "=f"(y) : "f"(x)); return y;
}

#if HAS_TC
__device__ __forceinline__ uint32_t elect_one() {
    uint32_t p;
    asm volatile("{ .reg .pred p; elect.sync _|p, 0xFFFFFFFF; selp.b32 %0,1,0,p; }" : "=r"(p));
    return p;
}
__device__ __forceinline__ void mbar_init(uint32_t a, uint32_t cnt) {
    asm volatile("mbarrier.init.shared.b64 [%0], %1;" :: "r"(a), "r"(cnt) : "memory");
}
__device__ __forceinline__ void mbar_expect_tx(uint32_t a, uint32_t bytes) {
    asm volatile("mbarrier.arrive.expect_tx.shared.b64 _, [%0], %1;" :: "r"(a), "r"(bytes) : "memory");
}
__device__ __forceinline__ void mbar_arrive_leader(uint32_t a) {
    asm volatile("{ .reg .b32 la; and.b32 la, %0, 0xFEFFFFFF;\n"
                 "mbarrier.arrive.shared::cluster.b64 _, [la]; }" :: "r"(a) : "memory");
}
__device__ __forceinline__ void mbar_wait_acq(uint32_t a, uint32_t ph) {
    asm volatile("{ .reg .pred P;\n"
                 "W_%=: mbarrier.try_wait.parity.acquire.cta.shared::cta.b64 P, [%0], %1;\n"
                 "@!P bra W_%=; }" :: "r"(a), "r"(ph) : "memory");
}
__device__ __forceinline__ void mbar_wait_rlx(uint32_t a, uint32_t ph) {
    asm volatile("{ .reg .pred P;\n"
                 "W_%=: mbarrier.try_wait.parity.relaxed.cta.shared::cta.b64 P, [%0], %1;\n"
                 "@!P bra W_%=; }" :: "r"(a), "r"(ph) : "memory");
}
// cg2 TMA: both CTAs execute; complete_tx targets the LEADER's barrier (bit 24 cleared)
__device__ __forceinline__ void tma2d_cg2(uint32_t dst, const CUtensorMap* m, int x, int y, uint32_t mbar) {
    asm volatile("{ .reg .b32 lb; and.b32 lb, %4, 0xFEFFFFFF;\n"
                 "cp.async.bulk.tensor.2d.cta_group::2.shared::cluster.global.tile.mbarrier::complete_tx::bytes "
                 "[%0], [%1, {%2, %3}], [lb]; }"
                 :: "r"(dst), "l"(m), "r"(x), "r"(y), "r"(mbar) : "memory");
}
__device__ __forceinline__ void tc_alloc_cg2(uint32_t smem_res, uint32_t ncols) {
    asm volatile("tcgen05.alloc.cta_group::2.sync.aligned.shared::cta.b32 [%0], %1;"
                 :: "r"(smem_res), "r"(ncols) : "memory");
}
__device__ __forceinline__ void tc_dealloc_cg2(uint32_t tmem, uint32_t ncols) {
    asm volatile("tcgen05.dealloc.cta_group::2.sync.aligned.b32 %0, %1;" :: "r"(tmem), "r"(ncols));
}
__device__ __forceinline__ void tc_relinq_cg2() {
    asm volatile("tcgen05.relinquish_alloc_permit.cta_group::2.sync.aligned;");
}
__device__ __forceinline__ void tc_commit_mc_cg2(uint32_t mbar) {
    asm volatile("tcgen05.commit.cta_group::2.mbarrier::arrive::one.shared::cluster.multicast::cluster.b64 [%0], %1;"
                 :: "r"(mbar), "h"((uint16_t)3) : "memory");
}
__device__ __forceinline__ void tc_fence_after() {
    asm volatile("tcgen05.fence::after_thread_sync;" ::: "memory");
}
__device__ __forceinline__ void tc_fence_before() {
    asm volatile("tcgen05.fence::before_thread_sync;" ::: "memory");
}
__device__ __forceinline__ void tc_wait_ld() {
    asm volatile("tcgen05.wait::ld.sync.aligned;" ::: "memory");
}
__device__ __forceinline__ void fence_proxy_async_cta() {
    asm volatile("fence.proxy.async.shared::cta;" ::: "memory");
}
__device__ __forceinline__ void mma_f16_ss_cg2(uint32_t d, uint64_t a, uint64_t b, uint32_t idesc, int acc) {
    asm volatile("{ .reg .pred p; setp.ne.u32 p, %4, 0;\n"
                 "tcgen05.mma.cta_group::2.kind::f16 [%0], %1, %2, %3, {%5,%5,%5,%5,%5,%5,%5,%5}, p; }"
                 :: "r"(d), "l"(a), "l"(b), "r"(idesc), "r"(acc), "r"(0u) : "memory");
}
__device__ __forceinline__ void ldtm_x32(uint32_t* r, uint32_t addr) {
    asm volatile("tcgen05.ld.sync.aligned.32x32b.x32.b32 "
                 "{%0,%1,%2,%3,%4,%5,%6,%7,%8,%9,%10,%11,%12,%13,%14,%15,"
                 "%16,%17,%18,%19,%20,%21,%22,%23,%24,%25,%26,%27,%28,%29,%30,%31}, [%32];"
                 : "=r"(r[0]), "=r"(r[1]), "=r"(r[2]), "=r"(r[3]), "=r"(r[4]), "=r"(r[5]),
                   "=r"(r[6]), "=r"(r[7]), "=r"(r[8]), "=r"(r[9]), "=r"(r[10]), "=r"(r[11]),
                   "=r"(r[12]), "=r"(r[13]), "=r"(r[14]), "=r"(r[15]), "=r"(r[16]), "=r"(r[17]),
                   "=r"(r[18]), "=r"(r[19]), "=r"(r[20]), "=r"(r[21]), "=r"(r[22]), "=r"(r[23]),
                   "=r"(r[24]), "=r"(r[25]), "=r"(r[26]), "=r"(r[27]), "=r"(r[28]), "=r"(r[29]),
                   "=r"(r[30]), "=r"(r[31])
                 : "r"(addr));
}
__device__ __forceinline__ void cluster_sync() {
    asm volatile("barrier.cluster.arrive.aligned;" ::: "memory");
    asm volatile("barrier.cluster.wait.aligned;" ::: "memory");
}
#endif  // HAS_TC

// ---------------------------------------------------------------------------
// Kernel 1: L2-normalize rows of z1, z2 -> bf16
// ---------------------------------------------------------------------------
__global__ void normalize_kernel(const float* __restrict__ z1,
                                 const float* __restrict__ z2)
{
    int b = blockIdx.x;
    int mat = b >> 12;
    int row = b & (N_ROWS - 1);
    const float* src = mat ? z2 : z1;
    __nv_bfloat16* dst = mat ? g_z2n : g_z1n;

    int t = threadIdx.x;
    float4 v = reinterpret_cast<const float4*>(src + (size_t)row * D_DIM)[t];
    float s = v.x * v.x + v.y * v.y + v.z * v.z + v.w * v.w;
    #pragma unroll
    for (int o = 16; o > 0; o >>= 1) s += __shfl_xor_sync(0xffffffffu, s, o);
    __shared__ float sh[8];
    if ((t & 31) == 0) sh[t >> 5] = s;
    __syncthreads();
    if (t < 8) {
        float x = sh[t];
        #pragma unroll
        for (int o = 4; o > 0; o >>= 1) x += __shfl_xor_sync(0xffu, x, o);
        if (t == 0) sh[0] = x;
    }
    __syncthreads();
    float inv = 1.0f / fmaxf(sqrtf(sh[0]), 1e-12f);

    __nv_bfloat162 lo = __floats2bfloat162_rn(v.x * inv, v.y * inv);
    __nv_bfloat162 hi = __floats2bfloat162_rn(v.z * inv, v.w * inv);
    uint2 pk;
    pk.x = reinterpret_cast<unsigned&>(lo);
    pk.y = reinterpret_cast<unsigned&>(hi);
    *reinterpret_cast<uint2*>(dst + (size_t)row * D_DIM + t * 4) = pk;
}

// ---------------------------------------------------------------------------
// Kernel 2: persistent cg2 (2-CTA) tcgen05 GEMM + fused exp/rowsum/diag
// grid = 128 CTAs (64 clusters of 2) x 192 threads.
// warps 0-3: epilogue, warp 4: TMA producer (both ranks), warp 5: MMA (rank 0)
// Each cluster: 4 tiles of 256x256.  Per CTA: A = its 128 rows, B = its 128 cols.
// ---------------------------------------------------------------------------
__global__ void __launch_bounds__(192, 1)
#if HAS_TC
__cluster_dims__(2, 1, 1)
#endif
gemm_lse_tc_kernel(const __grid_constant__ CUtensorMap tmA,
                   const __grid_constant__ CUtensorMap tmB)
{
#if HAS_TC
    extern __shared__ char smem[];
    const uint32_t sb = smem_u32(smem);
    const int tid  = threadIdx.x;
    const int warp = tid >> 5;
    const int lane = tid & 31;
    const int cid  = blockIdx.x >> 1;
    const int rank = blockIdx.x & 1;

    if (warp == 5) tc_alloc_cg2(sb + SMEM_TMEM, 512);
    if (tid == 0) {
        #pragma unroll
        for (int s = 0; s < STAGES; s++) {
            mbar_init(sb + SMEM_FULL  + s * 8, 1);   // leader: expect_tx arrive
            mbar_init(sb + SMEM_EMPTY + s * 8, 1);   // multicast commit
        }
        mbar_init(sb + SMEM_TDONE,     1);           // multicast commit
        mbar_init(sb + SMEM_TDONE + 8, 1);
        mbar_init(sb + SMEM_DFREE,     8);           // 4 warps x 2 CTAs
        mbar_init(sb + SMEM_DFREE + 8, 8);
        fence_proxy_async_cta();
    }
    __syncthreads();
    cluster_sync();   // peer barriers + TMEM alloc visible before multicast traffic

    uint32_t tbase;
    asm volatile("ld.shared.b32 %0, [%1];" : "=r"(tbase) : "r"(sb + SMEM_TMEM));

    if (warp == 4) {
        // ---- TMA producer (both ranks, one elected thread each) ----
        if (elect_one()) {
            int c = 0;
            for (int i = 0; i < TILES_PER_CL; i++) {
                int t = cid + i * NUM_CLUSTERS;
                int aRow = ((t >> 4) << 8) + rank * 128;   // this CTA's 128 A-rows
                int bRow = ((t & 15) << 8) + rank * 128;   // this CTA's 128 B-cols
                for (int ch = 0; ch < NUM_CHUNKS; ch++, c++) {
                    int s = c & 3;
                    mbar_wait_rlx(sb + SMEM_EMPTY + s * 8, ((c >> 2) & 1) ^ 1);
                    if (rank == 0)
                        mbar_expect_tx(sb + SMEM_FULL + s * 8, EXPECT_BYTES);
                    uint32_t base = sb + SMEM_STAGE + s * STAGE_BYTES;
                    tma2d_cg2(base + A_OFF, &tmA, ch * CHUNK_K, aRow, sb + SMEM_FULL + s * 8);
                    tma2d_cg2(base + B_OFF, &tmB, ch * CHUNK_K, bRow, sb + SMEM_FULL + s * 8);
                }
            }
        }
    } else if (warp == 5) {
        // ---- MMA issue (leader CTA only) ----
        if (rank == 0) {
            int c = 0;
            int phw[2] = {1, 1};
            for (int i = 0; i < TILES_PER_CL; i++) {
                int p = i & 1;
                mbar_wait_rlx(sb + SMEM_DFREE + p * 8, phw[p]);
                phw[p] ^= 1;
                uint32_t d = tbase + p * TILE;
                for (int ch = 0; ch < NUM_CHUNKS; ch++, c++) {
                    int s = c & 3;
                    mbar_wait_acq(sb + SMEM_FULL + s * 8, (c >> 2) & 1);
                    if (elect_one()) {
                        uint32_t base = sb + SMEM_STAGE + s * STAGE_BYTES;
                        uint64_t aD = DESC_BASE | (uint64_t)(((base + A_OFF) >> 4) & 0x3FFF);
                        uint64_t bD = DESC_BASE | (uint64_t)(((base + B_OFF) >> 4) & 0x3FFF);
                        #pragma unroll
                        for (int j = 0; j < 4; j++)   // K=16 per MMA, 64-col chunk
                            mma_f16_ss_cg2(d, aD + j * 2, bD + j * 2, MMA_IDESC, (ch > 0) | (j > 0));
                        tc_commit_mc_cg2(sb + SMEM_EMPTY + s * 8);
                    }
                }
                if (elect_one()) tc_commit_mc_cg2(sb + SMEM_TDONE + p * 8);
            }
        }
    } else {
        // ---- epilogue warps 0..3 (each CTA reads its own 128-row TMEM half) ----
        const float K1   = 20.609929155556624f;   // log2(e)/0.07
        const float INVT = 14.285714285714286f;   // 1/0.07
        int phe[2] = {0, 0};
        for (int i = 0; i < TILES_PER_CL; i++) {
            int p = i & 1;
            int t = cid + i * NUM_CLUSTERS;
            int rowBase = (t >> 4) << 8;
            int colBase = (t & 15) << 8;
            mbar_wait_acq(sb + SMEM_TDONE + p * 8, phe[p]);
            phe[p] ^= 1;
            tc_fence_after();

            int grow = rowBase + rank * 128 + warp * 32 + lane;
            int tgtC = grow - colBase;
            bool hasD = (tgtC >= 0) && (tgtC < TILE);
            float dval = 0.f;
            float s0 = 0.f, s1 = 0.f, s2 = 0.f, s3 = 0.f;

            #pragma unroll
            for (int chn = 0; chn < TILE / 32; chn++) {
                uint32_t r[32];
                ldtm_x32(r, tbase + p * TILE + chn * 32);
                tc_wait_ld();
                #pragma unroll
                for (int q = 0; q < 32; q += 4) {
                    s0 += ex2f(__uint_as_float(r[q    ]) * K1);
                    s1 += ex2f(__uint_as_float(r[q + 1]) * K1);
                    s2 += ex2f(__uint_as_float(r[q + 2]) * K1);
                    s3 += ex2f(__uint_as_float(r[q + 3]) * K1);
                }
                if (hasD && ((tgtC >> 5) == chn)) dval = __uint_as_float(r[tgtC & 31]);
            }
            tc_fence_before();
            __syncwarp();
            if (lane == 0) mbar_arrive_leader(sb + SMEM_DFREE + p * 8);

            g_partial[(size_t)grow * NT + (t & 15)] = (s0 + s1) + (s2 + s3);
            if (hasD) g_diag[grow] = dval * INVT;
        }
    }

    __syncthreads();
    if (warp == 5) {
        tc_relinq_cg2();
        tc_dealloc_cg2(tbase, 512);
    }
    cluster_sync();   // no CTA exits while peer multicast may be in flight
#endif  // HAS_TC
}

// ---------------------------------------------------------------------------
// Kernel 3: fused tail — per-row loss + global mean, single block
// ---------------------------------------------------------------------------
__global__ void __launch_bounds__(1024, 1) tail_kernel(float* __restrict__ out)
{
    int t = threadIdx.x;
    double acc = 0.0;
    #pragma unroll
    for (int i = 0; i < N_ROWS / 1024; i++) {
        int row = t + i * 1024;
        const float4* p = reinterpret_cast<const float4*>(g_partial + (size_t)row * NT);
        float4 a = p[0], b = p[1], c = p[2], d = p[3];
        float s = (((a.x + a.y) + (a.z + a.w)) + ((b.x + b.y) + (b.z + b.w)))
                + (((c.x + c.y) + (c.z + c.w)) + ((d.x + d.y) + (d.z + d.w)));
        acc += (double)(logf(s) - g_diag[row]);
    }
    #pragma unroll
    for (int o = 16; o > 0; o >>= 1) acc += __shfl_xor_sync(0xffffffffu, acc, o);
    __shared__ double sh[32];
    if ((t & 31) == 0) sh[t >> 5] = acc;
    __syncthreads();
    if (t < 32) {
        double x = sh[t];
        #pragma unroll
        for (int o = 16; o > 0; o >>= 1) x += __shfl_xor_sync(0xffffffffu, x, o);
        if (t == 0) out[0] = (float)(x / (double)N_ROWS);
    }
}

// ---------------------------------------------------------------------------
extern "C" void kernel_launch(void* const* d_in, const int* in_sizes, int n_in,
                              void* d_out, int out_size)
{
    const float* z1 = (const float*)d_in[0];
    const float* z2 = (const float*)d_in[1];
    float* out = (float*)d_out;

    // Host-side TMA descriptor construction (pure computation, every call)
    void *pa = nullptr, *pb = nullptr;
    cudaGetSymbolAddress(&pa, g_z1n);
    cudaGetSymbolAddress(&pb, g_z2n);

    typedef CUresult (*EncFn)(CUtensorMap*, CUtensorMapDataType, cuuint32_t, void*,
                              const cuuint64_t*, const cuuint64_t*, const cuuint32_t*,
                              const cuuint32_t*, CUtensorMapInterleave, CUtensorMapSwizzle,
                              CUtensorMapL2promotion, CUtensorMapFloatOOBfill);
    void* h = dlopen("libcuda.so.1", RTLD_NOW | RTLD_GLOBAL);
    if (!h) h = dlopen("libcuda.so", RTLD_NOW | RTLD_GLOBAL);
    EncFn enc = h ? (EncFn)dlsym(h, "cuTensorMapEncodeTiled") : nullptr;

    CUtensorMap tmA = {}, tmB = {};
    cuuint64_t dims[2]    = {D_DIM, N_ROWS};
    cuuint64_t strides[1] = {D_DIM * 2};
    cuuint32_t box[2]     = {CHUNK_K, 128};    // 128B x 128 rows per TMA
    cuuint32_t es[2]      = {1, 1};
    if (enc) {
        enc(&tmA, CU_TENSOR_MAP_DATA_TYPE_BFLOAT16, 2, pa, dims, strides, box, es,
            CU_TENSOR_MAP_INTERLEAVE_NONE, CU_TENSOR_MAP_SWIZZLE_128B,
            CU_TENSOR_MAP_L2_PROMOTION_L2_128B, CU_TENSOR_MAP_FLOAT_OOB_FILL_NONE);
        enc(&tmB, CU_TENSOR_MAP_DATA_TYPE_BFLOAT16, 2, pb, dims, strides, box, es,
            CU_TENSOR_MAP_INTERLEAVE_NONE, CU_TENSOR_MAP_SWIZZLE_128B,
            CU_TENSOR_MAP_L2_PROMOTION_L2_128B, CU_TENSOR_MAP_FLOAT_OOB_FILL_NONE);
    }

    cudaFuncSetAttribute(gemm_lse_tc_kernel,
                         cudaFuncAttributeMaxDynamicSharedMemorySize, SMEM_TOTAL);

    normalize_kernel<<<2 * N_ROWS, 256>>>(z1, z2);
    gemm_lse_tc_kernel<<<GRID_GEMM, 192, SMEM_TOTAL>>>(tmA, tmB);
    tail_kernel<<<1, 1024>>>(out);
}

// round 5
// speedup vs baseline: 3.8529x; 1.3979x over previous
#include <cuda_runtime.h>
#include <cuda.h>
#include <cuda_bf16.h>
#include <cuda_fp8.h>
#include <math.h>
#include <stdint.h>
#include <dlfcn.h>

// ---- feature probe: tcgen05/cg2 need arch-specific (sm_103a) pass ----
#if defined(__CUDA_ARCH_FEAT_SM103_ALL) || \
    (defined(__CUDA_ARCH_SPECIFIC__) && (__CUDA_ARCH_SPECIFIC__ == 1030))
#define HAS_TC 1
#else
#define HAS_TC 0
#endif

// ---------------- problem constants ----------------
#define N_ROWS 4096
#define D_DIM  1024
#define TILE   256                         // 256x256 output tiles (cg2 pair)
#define NT     (N_ROWS / TILE)             // 16 column tiles -> 16 partials/row
#define NUM_TILES (NT * NT)                // 256
#define GRID_GEMM 128                      // 64 clusters of 2
#define NUM_CLUSTERS (GRID_GEMM / 2)       // 64
#define TILES_PER_CL (NUM_TILES / NUM_CLUSTERS)  // 4
#define CHUNK_K 128                        // fp8: 128 elems = 128 bytes per row chunk
#define NUM_CHUNKS (D_DIM / CHUNK_K)       // 8
#define STAGES 6
#define TOTAL_CHUNKS (TILES_PER_CL * NUM_CHUNKS)  // 32

// FP8 scaling: store 64*v (e4m3), logits = acc / 4096
#define QSCALE 64.0f

// SMEM layout (per CTA)
#define SMEM_TMEM   0
#define SMEM_FULL   8      // 6 x 8B (leader-used)
#define SMEM_EMPTY  56     // 6 x 8B
#define SMEM_TDONE  104    // 2 x 8B
#define SMEM_DFREE  120    // 2 x 8B (leader-used, count 8)
#define SMEM_STAGE  1024
#define A_OFF 0            // 128 rows x 128B = 16KB
#define B_OFF 16384        // 128 cols x 128B = 16KB
#define STAGE_BYTES 32768
#define SMEM_TOTAL (SMEM_STAGE + STAGES * STAGE_BYTES)  // 197632
#define EXPECT_BYTES (4 * 16384)   // A+B from both CTAs -> leader barrier

// idesc: kind::f8f6f4, dtype F32 (bits[4:5]=1), atype=btype=E4M3 (0),
// N=256 (bits[17:23)), M_total=256 (bits[24:29))
#define MMA_IDESC ((1u<<4)|((TILE/8)<<17)|((TILE/16)<<24))

// SW128 K-major smem descriptor base (layout=2, version=1, SBO=64, LBO=1)
static __device__ constexpr uint64_t DESC_BASE =
    (uint64_t(2) << 61) | (uint64_t(1) << 46) | (uint64_t(64) << 32) | (uint64_t(1) << 16);

// ---------------- device scratch (no cudaMalloc allowed) ----------------
__device__ __align__(1024) unsigned char g_z1q[N_ROWS * D_DIM];
__device__ __align__(1024) unsigned char g_z2q[N_ROWS * D_DIM];
__device__ float g_partial[N_ROWS * NT];
__device__ float g_diag[N_ROWS];

// ---------------- PTX helpers ----------------
__device__ __forceinline__ uint32_t smem_u32(const void* p) {
    uint32_t a;
    asm("{ .reg .u64 t; cvta.to.shared.u64 t, %1; cvt.u32.u64 %0, t; }" : "=r"(a) : "l"(p));
    return a;
}
__device__ __forceinline__ float ex2f(float x) {
    float y; asm("ex2.approx.f32 %0, %1;" : "=f"(y) : "f"(x)); return y;
}

#if HAS_TC
__device__ __forceinline__ uint32_t elect_one() {
    uint32_t p;
    asm volatile("{ .reg .pred p; elect.sync _|p, 0xFFFFFFFF; selp.b32 %0,1,0,p; }" : "=r"(p));
    return p;
}
__device__ __forceinline__ void mbar_init(uint32_t a, uint32_t cnt) {
    asm volatile("mbarrier.init.shared.b64 [%0], %1;" :: "r"(a), "r"(cnt) : "memory");
}
__device__ __forceinline__ void mbar_expect_tx(uint32_t a, uint32_t bytes) {
    asm volatile("mbarrier.arrive.expect_tx.shared.b64 _, [%0], %1;" :: "r"(a), "r"(bytes) : "memory");
}
__device__ __forceinline__ void mbar_arrive_leader(uint32_t a) {
    asm volatile("{ .reg .b32 la; and.b32 la, %0, 0xFEFFFFFF;\n"
                 "mbarrier.arrive.shared::cluster.b64 _, [la]; }" :: "r"(a) : "memory");
}
__device__ __forceinline__ void mbar_wait_acq(uint32_t a, uint32_t ph) {
    asm volatile("{ .reg .pred P;\n"
                 "W_%=: mbarrier.try_wait.parity.acquire.cta.shared::cta.b64 P, [%0], %1;\n"
                 "@!P bra W_%=; }" :: "r"(a), "r"(ph) : "memory");
}
__device__ __forceinline__ void mbar_wait_rlx(uint32_t a, uint32_t ph) {
    asm volatile("{ .reg .pred P;\n"
                 "W_%=: mbarrier.try_wait.parity.relaxed.cta.shared::cta.b64 P, [%0], %1;\n"
                 "@!P bra W_%=; }" :: "r"(a), "r"(ph) : "memory");
}
// cg2 TMA: both CTAs execute; complete_tx targets the LEADER's barrier (bit 24 cleared)
__device__ __forceinline__ void tma2d_cg2(uint32_t dst, const CUtensorMap* m, int x, int y, uint32_t mbar) {
    asm volatile("{ .reg .b32 lb; and.b32 lb, %4, 0xFEFFFFFF;\n"
                 "cp.async.bulk.tensor.2d.cta_group::2.shared::cluster.global.tile.mbarrier::complete_tx::bytes "
                 "[%0], [%1, {%2, %3}], [lb]; }"
                 :: "r"(dst), "l"(m), "r"(x), "r"(y), "r"(mbar) : "memory");
}
__device__ __forceinline__ void tc_alloc_cg2(uint32_t smem_res, uint32_t ncols) {
    asm volatile("tcgen05.alloc.cta_group::2.sync.aligned.shared::cta.b32 [%0], %1;"
                 :: "r"(smem_res), "r"(ncols) : "memory");
}
__device__ __forceinline__ void tc_dealloc_cg2(uint32_t tmem, uint32_t ncols) {
    asm volatile("tcgen05.dealloc.cta_group::2.sync.aligned.b32 %0, %1;" :: "r"(tmem), "r"(ncols));
}
__device__ __forceinline__ void tc_relinq_cg2() {
    asm volatile("tcgen05.relinquish_alloc_permit.cta_group::2.sync.aligned;");
}
__device__ __forceinline__ void tc_commit_mc_cg2(uint32_t mbar) {
    asm volatile("tcgen05.commit.cta_group::2.mbarrier::arrive::one.shared::cluster.multicast::cluster.b64 [%0], %1;"
                 :: "r"(mbar), "h"((uint16_t)3) : "memory");
}
__device__ __forceinline__ void tc_fence_after() {
    asm volatile("tcgen05.fence::after_thread_sync;" ::: "memory");
}
__device__ __forceinline__ void tc_fence_before() {
    asm volatile("tcgen05.fence::before_thread_sync;" ::: "memory");
}
__device__ __forceinline__ void tc_wait_ld() {
    asm volatile("tcgen05.wait::ld.sync.aligned;" ::: "memory");
}
__device__ __forceinline__ void fence_proxy_async_cta() {
    asm volatile("fence.proxy.async.shared::cta;" ::: "memory");
}
// dense fp8 MMA (kind::f8f6f4), cta_group::2
__device__ __forceinline__ void mma_f8_ss_cg2(uint32_t d, uint64_t a, uint64_t b, uint32_t idesc, int acc) {
    asm volatile("{ .reg .pred p; setp.ne.u32 p, %4, 0;\n"
                 "tcgen05.mma.cta_group::2.kind::f8f6f4 [%0], %1, %2, %3, {%5,%5,%5,%5,%5,%5,%5,%5}, p; }"
                 :: "r"(d), "l"(a), "l"(b), "r"(idesc), "r"(acc), "r"(0u) : "memory");
}
__device__ __forceinline__ void ldtm_x32(uint32_t* r, uint32_t addr) {
    asm volatile("tcgen05.ld.sync.aligned.32x32b.x32.b32 "
                 "{%0,%1,%2,%3,%4,%5,%6,%7,%8,%9,%10,%11,%12,%13,%14,%15,"
                 "%16,%17,%18,%19,%20,%21,%22,%23,%24,%25,%26,%27,%28,%29,%30,%31}, [%32];"
                 : "=r"(r[0]), "=r"(r[1]), "=r"(r[2]), "=r"(r[3]), "=r"(r[4]), "=r"(r[5]),
                   "=r"(r[6]), "=r"(r[7]), "=r"(r[8]), "=r"(r[9]), "=r"(r[10]), "=r"(r[11]),
                   "=r"(r[12]), "=r"(r[13]), "=r"(r[14]), "=r"(r[15]), "=r"(r[16]), "=r"(r[17]),
                   "=r"(r[18]), "=r"(r[19]), "=r"(r[20]), "=r"(r[21]), "=r"(r[22]), "=r"(r[23]),
                   "=r"(r[24]), "=r"(r[25]), "=r"(r[26]), "=r"(r[27]), "=r"(r[28]), "=r"(r[29]),
                   "=r"(r[30]), "=r"(r[31])
                 : "r"(addr));
}
__device__ __forceinline__ void cluster_sync() {
    asm volatile("barrier.cluster.arrive.aligned;" ::: "memory");
    asm volatile("barrier.cluster.wait.aligned;" ::: "memory");
}
#endif  // HAS_TC

// ---------------------------------------------------------------------------
// Kernel 1: L2-normalize rows, scale by 64, emit e4m3. Warp-per-row.
// grid = 1024 blocks x 256 threads (8 warps = 8 rows per block)
// ---------------------------------------------------------------------------
__global__ void __launch_bounds__(256, 4)
normalize_kernel(const float* __restrict__ z1, const float* __restrict__ z2)
{
    int gw   = blockIdx.x * 8 + (threadIdx.x >> 5);   // global warp = row id
    int lane = threadIdx.x & 31;
    int mat  = gw >> 12;
    int row  = gw & (N_ROWS - 1);
    const float* src = mat ? z2 : z1;
    unsigned char* dst = mat ? g_z2q : g_z1q;

    const float4* s4 = reinterpret_cast<const float4*>(src + (size_t)row * D_DIM);
    float4 v[8];
    float ss = 0.f;
    #pragma unroll
    for (int j = 0; j < 8; j++) {
        v[j] = s4[j * 32 + lane];
        ss += v[j].x * v[j].x + v[j].y * v[j].y + v[j].z * v[j].z + v[j].w * v[j].w;
    }
    #pragma unroll
    for (int o = 16; o > 0; o >>= 1) ss += __shfl_xor_sync(0xffffffffu, ss, o);

    float inv = QSCALE / fmaxf(sqrtf(ss), 1e-12f);

    uint32_t* d4 = reinterpret_cast<uint32_t*>(dst + (size_t)row * D_DIM);
    #pragma unroll
    for (int j = 0; j < 8; j++) {
        float2 lo = make_float2(v[j].x * inv, v[j].y * inv);
        float2 hi = make_float2(v[j].z * inv, v[j].w * inv);
        uint32_t plo = __nv_cvt_float2_to_fp8x2(lo, __NV_SATFINITE, __NV_E4M3);
        uint32_t phi = __nv_cvt_float2_to_fp8x2(hi, __NV_SATFINITE, __NV_E4M3);
        d4[j * 32 + lane] = (plo & 0xFFFFu) | (phi << 16);
    }
}

// ---------------------------------------------------------------------------
// Kernel 2: persistent cg2 (2-CTA) tcgen05 FP8 GEMM + fused exp/rowsum/diag
// grid = 128 CTAs (64 clusters of 2) x 192 threads.
// warps 0-3: epilogue, warp 4: TMA producer (both ranks), warp 5: MMA (rank 0)
// Each cluster: 4 tiles of 256x256. Per CTA: A = its 128 rows, B = its 128 cols.
// ---------------------------------------------------------------------------
__global__ void __launch_bounds__(192, 1)
#if HAS_TC
__cluster_dims__(2, 1, 1)
#endif
gemm_lse_tc_kernel(const __grid_constant__ CUtensorMap tmA,
                   const __grid_constant__ CUtensorMap tmB)
{
#if HAS_TC
    extern __shared__ char smem[];
    const uint32_t sb = smem_u32(smem);
    const int tid  = threadIdx.x;
    const int warp = tid >> 5;
    const int lane = tid & 31;
    const int cid  = blockIdx.x >> 1;
    const int rank = blockIdx.x & 1;

    if (warp == 5) tc_alloc_cg2(sb + SMEM_TMEM, 512);
    if (tid == 0) {
        #pragma unroll
        for (int s = 0; s < STAGES; s++) {
            mbar_init(sb + SMEM_FULL  + s * 8, 1);   // leader: expect_tx arrive
            mbar_init(sb + SMEM_EMPTY + s * 8, 1);   // multicast commit
        }
        mbar_init(sb + SMEM_TDONE,     1);           // multicast commit
        mbar_init(sb + SMEM_TDONE + 8, 1);
        mbar_init(sb + SMEM_DFREE,     8);           // 4 warps x 2 CTAs
        mbar_init(sb + SMEM_DFREE + 8, 8);
        fence_proxy_async_cta();
    }
    __syncthreads();
    cluster_sync();   // peer barriers + TMEM alloc visible before multicast traffic

    uint32_t tbase;
    asm volatile("ld.shared.b32 %0, [%1];" : "=r"(tbase) : "r"(sb + SMEM_TMEM));

    if (warp == 4) {
        // ---- TMA producer (both ranks, one elected thread each) ----
        if (elect_one()) {
            int st = 0, ph = 1;   // empty-barrier cursor (starts passing)
            for (int i = 0; i < TILES_PER_CL; i++) {
                int t = cid + i * NUM_CLUSTERS;
                int aRow = ((t >> 4) << 8) + rank * 128;
                int bRow = ((t & 15) << 8) + rank * 128;
                for (int ch = 0; ch < NUM_CHUNKS; ch++) {
                    mbar_wait_rlx(sb + SMEM_EMPTY + st * 8, ph);
                    if (rank == 0)
                        mbar_expect_tx(sb + SMEM_FULL + st * 8, EXPECT_BYTES);
                    uint32_t base = sb + SMEM_STAGE + st * STAGE_BYTES;
                    tma2d_cg2(base + A_OFF, &tmA, ch * CHUNK_K, aRow, sb + SMEM_FULL + st * 8);
                    tma2d_cg2(base + B_OFF, &tmB, ch * CHUNK_K, bRow, sb + SMEM_FULL + st * 8);
                    if (++st == STAGES) { st = 0; ph ^= 1; }
                }
            }
        }
    } else if (warp == 5) {
        // ---- MMA issue (leader CTA only) ----
        if (rank == 0) {
            int st = 0, ph = 0;   // full-barrier cursor
            int phw[2] = {1, 1};
            for (int i = 0; i < TILES_PER_CL; i++) {
                int p = i & 1;
                mbar_wait_rlx(sb + SMEM_DFREE + p * 8, phw[p]);
                phw[p] ^= 1;
                uint32_t d = tbase + p * TILE;
                for (int ch = 0; ch < NUM_CHUNKS; ch++) {
                    mbar_wait_acq(sb + SMEM_FULL + st * 8, ph);
                    if (elect_one()) {
                        uint32_t base = sb + SMEM_STAGE + st * STAGE_BYTES;
                        uint64_t aD = DESC_BASE | (uint64_t)(((base + A_OFF) >> 4) & 0x3FFF);
                        uint64_t bD = DESC_BASE | (uint64_t)(((base + B_OFF) >> 4) & 0x3FFF);
                        #pragma unroll
                        for (int j = 0; j < 4; j++)   // K=32 per MMA (32B = 2 desc units)
                            mma_f8_ss_cg2(d, aD + j * 2, bD + j * 2, MMA_IDESC, (ch > 0) | (j > 0));
                        tc_commit_mc_cg2(sb + SMEM_EMPTY + st * 8);
                    }
                    if (++st == STAGES) { st = 0; ph ^= 1; }
                }
                if (elect_one()) tc_commit_mc_cg2(sb + SMEM_TDONE + p * 8);
            }
        }
    } else {
        // ---- epilogue warps 0..3 (each CTA reads its own 128-row TMEM half) ----
        // logits = acc / 4096 (QSCALE^2); exp via ex2
        const float K1Q   = 20.609929155556624f / 4096.0f;   // log2(e)/0.07/4096
        const float INVTQ = 14.285714285714286f / 4096.0f;   // 1/0.07/4096
        int phe[2] = {0, 0};
        for (int i = 0; i < TILES_PER_CL; i++) {
            int p = i & 1;
            int t = cid + i * NUM_CLUSTERS;
            int rowBase = (t >> 4) << 8;
            int colBase = (t & 15) << 8;
            mbar_wait_acq(sb + SMEM_TDONE + p * 8, phe[p]);
            phe[p] ^= 1;
            tc_fence_after();

            int grow = rowBase + rank * 128 + warp * 32 + lane;
            int tgtC = grow - colBase;
            bool hasD = (tgtC >= 0) && (tgtC < TILE);
            float dval = 0.f;
            float s0 = 0.f, s1 = 0.f, s2 = 0.f, s3 = 0.f;

            #pragma unroll
            for (int chn = 0; chn < TILE / 32; chn++) {
                uint32_t r[32];
                ldtm_x32(r, tbase + p * TILE + chn * 32);
                tc_wait_ld();
                #pragma unroll
                for (int q = 0; q < 32; q += 4) {
                    s0 += ex2f(__uint_as_float(r[q    ]) * K1Q);
                    s1 += ex2f(__uint_as_float(r[q + 1]) * K1Q);
                    s2 += ex2f(__uint_as_float(r[q + 2]) * K1Q);
                    s3 += ex2f(__uint_as_float(r[q + 3]) * K1Q);
                }
                if (hasD && ((tgtC >> 5) == chn)) dval = __uint_as_float(r[tgtC & 31]);
            }
            tc_fence_before();
            __syncwarp();
            if (lane == 0) mbar_arrive_leader(sb + SMEM_DFREE + p * 8);

            g_partial[(size_t)grow * NT + (t & 15)] = (s0 + s1) + (s2 + s3);
            if (hasD) g_diag[grow] = dval * INVTQ;
        }
    }

    __syncthreads();
    if (warp == 5) {
        tc_relinq_cg2();
        tc_dealloc_cg2(tbase, 512);
    }
    cluster_sync();   // no CTA exits while peer multicast may be in flight
#endif  // HAS_TC
}

// ---------------------------------------------------------------------------
// Kernel 3: fused tail — per-row loss + global mean, single block
// ---------------------------------------------------------------------------
__global__ void __launch_bounds__(1024, 1) tail_kernel(float* __restrict__ out)
{
    int t = threadIdx.x;
    double acc = 0.0;
    #pragma unroll
    for (int i = 0; i < N_ROWS / 1024; i++) {
        int row = t + i * 1024;
        const float4* p = reinterpret_cast<const float4*>(g_partial + (size_t)row * NT);
        float4 a = p[0], b = p[1], c = p[2], d = p[3];
        float s = (((a.x + a.y) + (a.z + a.w)) + ((b.x + b.y) + (b.z + b.w)))
                + (((c.x + c.y) + (c.z + c.w)) + ((d.x + d.y) + (d.z + d.w)));
        acc += (double)(logf(s) - g_diag[row]);
    }
    #pragma unroll
    for (int o = 16; o > 0; o >>= 1) acc += __shfl_xor_sync(0xffffffffu, acc, o);
    __shared__ double sh[32];
    if ((t & 31) == 0) sh[t >> 5] = acc;
    __syncthreads();
    if (t < 32) {
        double x = sh[t];
        #pragma unroll
        for (int o = 16; o > 0; o >>= 1) x += __shfl_xor_sync(0xffffffffu, x, o);
        if (t == 0) out[0] = (float)(x / (double)N_ROWS);
    }
}

// ---------------------------------------------------------------------------
extern "C" void kernel_launch(void* const* d_in, const int* in_sizes, int n_in,
                              void* d_out, int out_size)
{
    const float* z1 = (const float*)d_in[0];
    const float* z2 = (const float*)d_in[1];
    float* out = (float*)d_out;

    // Host-side TMA descriptor construction (pure computation, every call)
    void *pa = nullptr, *pb = nullptr;
    cudaGetSymbolAddress(&pa, g_z1q);
    cudaGetSymbolAddress(&pb, g_z2q);

    typedef CUresult (*EncFn)(CUtensorMap*, CUtensorMapDataType, cuuint32_t, void*,
                              const cuuint64_t*, const cuuint64_t*, const cuuint32_t*,
                              const cuuint32_t*, CUtensorMapInterleave, CUtensorMapSwizzle,
                              CUtensorMapL2promotion, CUtensorMapFloatOOBfill);
    void* h = dlopen("libcuda.so.1", RTLD_NOW | RTLD_GLOBAL);
    if (!h) h = dlopen("libcuda.so", RTLD_NOW | RTLD_GLOBAL);
    EncFn enc = h ? (EncFn)dlsym(h, "cuTensorMapEncodeTiled") : nullptr;

    CUtensorMap tmA = {}, tmB = {};
    cuuint64_t dims[2]    = {D_DIM, N_ROWS};      // 1024 fp8 bytes per row
    cuuint64_t strides[1] = {D_DIM};              // 1024 bytes
    cuuint32_t box[2]     = {CHUNK_K, 128};       // 128B x 128 rows per TMA
    cuuint32_t es[2]      = {1, 1};
    if (enc) {
        enc(&tmA, CU_TENSOR_MAP_DATA_TYPE_UINT8, 2, pa, dims, strides, box, es,
            CU_TENSOR_MAP_INTERLEAVE_NONE, CU_TENSOR_MAP_SWIZZLE_128B,
            CU_TENSOR_MAP_L2_PROMOTION_L2_128B, CU_TENSOR_MAP_FLOAT_OOB_FILL_NONE);
        enc(&tmB, CU_TENSOR_MAP_DATA_TYPE_UINT8, 2, pb, dims, strides, box, es,
            CU_TENSOR_MAP_INTERLEAVE_NONE, CU_TENSOR_MAP_SWIZZLE_128B,
            CU_TENSOR_MAP_L2_PROMOTION_L2_128B, CU_TENSOR_MAP_FLOAT_OOB_FILL_NONE);
    }

    cudaFuncSetAttribute(gemm_lse_tc_kernel,
                         cudaFuncAttributeMaxDynamicSharedMemorySize, SMEM_TOTAL);

    normalize_kernel<<<1024, 256>>>(z1, z2);
    gemm_lse_tc_kernel<<<GRID_GEMM, 192, SMEM_TOTAL>>>(tmA, tmB);
    tail_kernel<<<1, 1024>>>(out);
}